// round 2
// baseline (speedup 1.0000x reference)
#include <cuda_runtime.h>

#define Bc 4
#define Hc 16
#define Sc 4096
#define Dc 64
#define BHc (Bc*Hc)        // 64
#define NCHUNK 16
#define CHUNK (Sc/NCHUNK)  // 256
#define TS 32

// Scratch (allocation-free per harness rules)
__device__ float g_pKV[NCHUNK][BHc][Dc*Dc];  // partial KV per S-chunk
__device__ float g_pKs[NCHUNK][BHc][Dc];     // partial Ksum per S-chunk
__device__ float g_KV[BHc][Dc*Dc];           // reduced KV
__device__ float g_Ks[BHc][Dc];              // reduced Ksum

typedef unsigned long long u64;

__device__ __forceinline__ u64 pack2(float lo, float hi){
    u64 r; asm("mov.b64 %0, {%1,%2};" : "=l"(r) : "f"(lo), "f"(hi)); return r;
}
__device__ __forceinline__ void unpack2(u64 v, float &lo, float &hi){
    asm("mov.b64 {%0,%1}, %2;" : "=f"(lo), "=f"(hi) : "l"(v));
}
// packed dual-fp32 FMA (FFMA2 in SASS; only reachable via PTX fma.rn.f32x2)
__device__ __forceinline__ void fma2(u64 &d, u64 a, u64 b){
    asm("fma.rn.f32x2 %0, %1, %2, %0;" : "+l"(d) : "l"(a), "l"(b));
}
// elu(x)+1 feature map
__device__ __forceinline__ float feat(float x){
    return x > 0.f ? x + 1.f : __expf(x);
}

// ---------------------------------------------------------------------------
// Phase 1: partial KV[d][e] = sum_s Kf[s][d]*V[s][e], partial Ksum[d]
// grid (BHc, NCHUNK), 128 threads. Thread tile 4(d) x 8(e).
// K stored in smem as DUPLICATED f32 pairs -> FFMA2 multiplier via LDS.128,
// zero register MOVs in the inner loop.
// ---------------------------------------------------------------------------
__global__ __launch_bounds__(128) void phase1_kernel(const float* __restrict__ K,
                                                     const float* __restrict__ V,
                                                     const float* __restrict__ mask){
    __shared__ __align__(16) u64   sKd[TS][Dc];   // dup pairs {k,k}, 16KB
    __shared__ __align__(16) float sV [TS][Dc];   // 8KB
    __shared__ float ksP[4][Dc];                  // per-warp ksum partials

    const int bh = blockIdx.x, ch = blockIdx.y;
    const int t  = threadIdx.x;
    const float* Kp = K    + ((size_t)bh*Sc + (size_t)ch*CHUNK)*Dc;
    const float* Vp = V    + ((size_t)bh*Sc + (size_t)ch*CHUNK)*Dc;
    const float* Mp = mask + (size_t)bh*Sc + (size_t)ch*CHUNK;

    // compute-tile mapping: 16 d-groups x 8 e-groups
    const int dy = t >> 3;            // 0..15
    const int ex = t & 7;             // 0..7
    const int d0 = dy*4, e0 = ex*8;

    // loader mapping
    const int lw   = t >> 5;          // warp 0..3
    const int lane = t & 31;

    u64 acc[4][4];
    #pragma unroll
    for (int i=0;i<4;i++)
        #pragma unroll
        for (int j=0;j<4;j++) acc[i][j]=pack2(0.f,0.f);

    float ksA = 0.f, ksB = 0.f;       // partial Ksum for d=2*lane, 2*lane+1

    for (int st = 0; st < CHUNK; st += TS){
        // --- load K (dup pairs, conflict-free STS.128) + accumulate ksum ---
        #pragma unroll
        for (int p = 0; p < 8; p++){
            int r = lw*8 + p;                  // warp lw owns rows lw*8..lw*8+7
            int s = st + r;
            float m = Mp[s];
            float2 k2 = *(const float2*)(Kp + (size_t)s*Dc + lane*2);
            float a = feat(k2.x)*m;
            float b = feat(k2.y)*m;
            ksA += a; ksB += b;
            *(float4*)&sKd[r][lane*2] = make_float4(a,a,b,b);
        }
        // --- load V (float4, conflict-free) ---
        {
            const int vr = t >> 4, vc = (t & 15)*4;
            #pragma unroll
            for (int p = 0; p < 4; p++){
                int r = vr + 8*p;
                int s = st + r;
                *(float4*)&sV[r][vc] = *(const float4*)(Vp + (size_t)s*Dc + vc);
            }
        }
        __syncthreads();

        // --- main GEMM: per s: 2 LDS.128 (k dup) + 2 LDS.128 (v) + 16 FFMA2 ---
        #pragma unroll
        for (int s = 0; s < TS; s++){
            ulonglong2 kA = *(const ulonglong2*)&sKd[s][d0];     // dup(k[d0]),dup(k[d0+1])
            ulonglong2 kB = *(const ulonglong2*)&sKd[s][d0+2];
            ulonglong2 vA = *(const ulonglong2*)&sV[s][e0];      // pairs (e0,e0+1),(e0+2,e0+3)
            ulonglong2 vB = *(const ulonglong2*)&sV[s][e0+4];
            fma2(acc[0][0], kA.x, vA.x); fma2(acc[0][1], kA.x, vA.y);
            fma2(acc[0][2], kA.x, vB.x); fma2(acc[0][3], kA.x, vB.y);
            fma2(acc[1][0], kA.y, vA.x); fma2(acc[1][1], kA.y, vA.y);
            fma2(acc[1][2], kA.y, vB.x); fma2(acc[1][3], kA.y, vB.y);
            fma2(acc[2][0], kB.x, vA.x); fma2(acc[2][1], kB.x, vA.y);
            fma2(acc[2][2], kB.x, vB.x); fma2(acc[2][3], kB.x, vB.y);
            fma2(acc[3][0], kB.y, vA.x); fma2(acc[3][1], kB.y, vA.y);
            fma2(acc[3][2], kB.y, vB.x); fma2(acc[3][3], kB.y, vB.y);
        }
        __syncthreads();
    }

    // --- epilogue: partial KV (store packed pairs directly) ---
    float* outKV = g_pKV[ch][bh];
    #pragma unroll
    for (int i = 0; i < 4; i++){
        *(ulonglong2*)(outKV + (size_t)(d0+i)*Dc + e0    ) = make_ulonglong2(acc[i][0], acc[i][1]);
        *(ulonglong2*)(outKV + (size_t)(d0+i)*Dc + e0 + 4) = make_ulonglong2(acc[i][2], acc[i][3]);
    }
    // --- ksum partials: warp-local d = 2*lane(,+1), reduce over 4 warps ---
    ksP[lw][lane*2]   = ksA;
    ksP[lw][lane*2+1] = ksB;
    __syncthreads();
    if (t < Dc){
        float s = ksP[0][t] + ksP[1][t] + ksP[2][t] + ksP[3][t];
        g_pKs[ch][bh][t] = s;
    }
}

// ---------------------------------------------------------------------------
// Reduce partials
// ---------------------------------------------------------------------------
__global__ void reduce_kernel(){
    const int idx = blockIdx.x*blockDim.x + threadIdx.x;
    const int nKV = BHc*Dc*Dc;
    if (idx < nKV){
        int bh = idx / (Dc*Dc), off = idx % (Dc*Dc);
        float s = 0.f;
        #pragma unroll
        for (int c = 0; c < NCHUNK; c++) s += g_pKV[c][bh][off];
        g_KV[bh][off] = s;
    } else {
        int j = idx - nKV;
        if (j < BHc*Dc){
            int bh = j / Dc, d = j % Dc;
            float s = 0.f;
            #pragma unroll
            for (int c = 0; c < NCHUNK; c++) s += g_pKs[c][bh][d];
            g_Ks[bh][d] = s;
        }
    }
}

// ---------------------------------------------------------------------------
// Phase 2: out[s][e] = Z[s] * sum_d Qf[s][d] * KV[d][e]
// grid (BHc, Sc/64), 128 threads. 64 s-rows/CTA. Thread tile 4(s) x 8(e).
// Qf is staged row-major, then rebuilt as DUPLICATED transposed pairs sQd[d][s]
// with conflict-free writes; inner loop has zero MOVs.
// ---------------------------------------------------------------------------
__global__ __launch_bounds__(128) void phase2_kernel(const float* __restrict__ Q,
                                                     float* __restrict__ out){
    __shared__ __align__(16) float sQ [64][Dc+1];  // staging (feat applied), pad->2-way reads
    __shared__ __align__(16) u64   sQd[Dc][64];    // dup transposed {q,q}, 32KB
    __shared__ __align__(16) float sKV[Dc][Dc];    // 16KB
    __shared__ float sKsum[Dc];
    __shared__ float sZ[64];

    const int bh = blockIdx.x, sb = blockIdx.y;
    const int t  = threadIdx.x;
    const float* Qp = Q + ((size_t)bh*Sc + (size_t)sb*64)*Dc;

    // --- stage Qf row-major ---
    {
        const int lr = t >> 4, lc = (t & 15)*4;
        #pragma unroll
        for (int p = 0; p < 8; p++){
            int r = lr + 8*p;
            float4 q4 = *(const float4*)(Qp + (size_t)r*Dc + lc);
            sQ[r][lc+0] = feat(q4.x);
            sQ[r][lc+1] = feat(q4.y);
            sQ[r][lc+2] = feat(q4.z);
            sQ[r][lc+3] = feat(q4.w);
        }
    }
    // --- load KV + Ksum ---
    {
        const float* kvp = g_KV[bh];
        #pragma unroll
        for (int p = 0; p < 8; p++){
            int i = t + 128*p;
            *(((float4*)&sKV[0][0]) + i) = *(((const float4*)kvp) + i);
        }
        if (t < Dc) sKsum[t] = g_Ks[bh][t];
    }
    __syncthreads();

    // --- build duplicated transposed Q: sQd[d][s] = {Qf[s][d], Qf[s][d]} ---
    {
        const int lw = t >> 5, lane = t & 31;
        #pragma unroll
        for (int p = 0; p < 16; p++){
            int d = lw + 4*p;
            float q0 = sQ[2*lane  ][d];
            float q1 = sQ[2*lane+1][d];
            *(float4*)&sQd[d][2*lane] = make_float4(q0,q0,q1,q1);  // conflict-free STS.128
        }
    }
    // --- Z per s-row ---
    if (t < 64){
        float z = 0.f;
        #pragma unroll 16
        for (int d = 0; d < Dc; d++) z += sQ[t][d] * sKsum[d];
        sZ[t] = 1.f / z;
    }
    __syncthreads();

    // compute-tile mapping: 16 s-groups x 8 e-groups
    const int sy = t >> 3;            // 0..15
    const int ex = t & 7;             // 0..7
    const int s0 = sy*4, e0 = ex*8;

    u64 acc[4][4];
    #pragma unroll
    for (int i=0;i<4;i++)
        #pragma unroll
        for (int j=0;j<4;j++) acc[i][j]=pack2(0.f,0.f);

    #pragma unroll 16
    for (int d = 0; d < Dc; d++){
        ulonglong2 qA = *(const ulonglong2*)&sQd[d][s0];      // dup(q[s0]),dup(q[s0+1])
        ulonglong2 qB = *(const ulonglong2*)&sQd[d][s0+2];
        ulonglong2 vA = *(const ulonglong2*)&sKV[d][e0];
        ulonglong2 vB = *(const ulonglong2*)&sKV[d][e0+4];
        fma2(acc[0][0], qA.x, vA.x); fma2(acc[0][1], qA.x, vA.y);
        fma2(acc[0][2], qA.x, vB.x); fma2(acc[0][3], qA.x, vB.y);
        fma2(acc[1][0], qA.y, vA.x); fma2(acc[1][1], qA.y, vA.y);
        fma2(acc[1][2], qA.y, vB.x); fma2(acc[1][3], qA.y, vB.y);
        fma2(acc[2][0], qB.x, vA.x); fma2(acc[2][1], qB.x, vA.y);
        fma2(acc[2][2], qB.x, vB.x); fma2(acc[2][3], qB.x, vB.y);
        fma2(acc[3][0], qB.y, vA.x); fma2(acc[3][1], qB.y, vA.y);
        fma2(acc[3][2], qB.y, vB.x); fma2(acc[3][3], qB.y, vB.y);
    }

    #pragma unroll
    for (int i = 0; i < 4; i++){
        float z = sZ[s0+i];
        float r0,r1,r2,r3,r4,r5,r6,r7;
        unpack2(acc[i][0], r0, r1);
        unpack2(acc[i][1], r2, r3);
        unpack2(acc[i][2], r4, r5);
        unpack2(acc[i][3], r6, r7);
        float* op = out + ((size_t)bh*Sc + (size_t)sb*64 + s0+i)*Dc + e0;
        *(float4*)(op    ) = make_float4(r0*z, r1*z, r2*z, r3*z);
        *(float4*)(op + 4) = make_float4(r4*z, r5*z, r6*z, r7*z);
    }
}

// ---------------------------------------------------------------------------
extern "C" void kernel_launch(void* const* d_in, const int* in_sizes, int n_in,
                              void* d_out, int out_size){
    const float* Q    = (const float*)d_in[0];
    const float* K    = (const float*)d_in[1];
    const float* V    = (const float*)d_in[2];
    const float* mask = (const float*)d_in[3];
    float* out = (float*)d_out;

    phase1_kernel<<<dim3(BHc, NCHUNK), 128>>>(K, V, mask);

    const int total = BHc*Dc*Dc + BHc*Dc;
    reduce_kernel<<<(total + 255)/256, 256>>>();

    phase2_kernel<<<dim3(BHc, Sc/64), 128>>>(Q, out);
}